// round 9
// baseline (speedup 1.0000x reference)
#include <cuda_runtime.h>
#include <cstdint>

// B=8, N=2048, F=D=128
//   H = A_hat @ X ; O = H @ W^T + b ; out = relu(LN(O)*gamma+beta)
//
// R7: few fat warps. CTA = 64 rows x 128 cols, 2 warps, warp tile 64x64
// (acc 128 regs, 32 independent HMMA per k8). 256 CTAs, 2/SM. CK=64, 2-stage
// cp.async pipe. ldmatrix operand fetch (A_hat native k-major; X pre-transposed).

#define BATCH 8
#define NN    2048
#define FF    128

#define ROWS  64
#define CK    64
#define NCH   (NN / CK)      // 32
#define PADA  68             // stage pitch floats (68 % 32 == 4 -> LDSM conflict-free)
#define PADH  132            // H / W pitch floats

#define ST_X_OFF   17408     // A part: 64*68*4
#define STAGE_B    52224     // + X part: 128*68*4 = 34816
#define SM_W_OFF   33792     // post-loop overlay: H 64*132*4 @0, W 128*132*4 @33792
#define SM_PAR_OFF 104448    // bias|gamma|beta 3*512
#define SM_RED_OFF 105984    // 64 rows x 2 warps x {s1,s2} = 1024 B
#define SM_TOTAL   107008

__device__ __align__(16) float g_Xt[BATCH * FF * NN];   // 8 MB scratch

__device__ __forceinline__ uint32_t smem_u32(const void* p) {
    uint32_t a;
    asm("{ .reg .u64 t; cvta.to.shared.u64 t, %1; cvt.u32.u64 %0, t; }" : "=r"(a) : "l"(p));
    return a;
}
__device__ __forceinline__ void cp16(uint32_t dst, const void* src) {
    asm volatile("cp.async.cg.shared.global [%0], [%1], 16;" :: "r"(dst), "l"(src) : "memory");
}
#define CP_COMMIT() asm volatile("cp.async.commit_group;" ::: "memory")

#define LDSM_X4(r0, r1, r2, r3, addr)                                           \
    asm volatile("ldmatrix.sync.aligned.m8n8.x4.shared.b16 {%0,%1,%2,%3}, [%4];"\
        : "=r"(r0), "=r"(r1), "=r"(r2), "=r"(r3) : "r"(addr))

#define MMA_TF32(d, av, bv)                                                     \
    asm volatile("mma.sync.aligned.m16n8k8.row.col.f32.tf32.tf32.f32 "          \
        "{%0,%1,%2,%3}, {%4,%5,%6,%7}, {%8,%9}, {%0,%1,%2,%3};"                 \
        : "+f"((d)[0]), "+f"((d)[1]), "+f"((d)[2]), "+f"((d)[3])                \
        : "r"((av)[0]), "r"((av)[1]), "r"((av)[2]), "r"((av)[3]),               \
          "r"((bv)[0]), "r"((bv)[1]))

// ---------------- k0: X transpose -> g_Xt[b][f][k] ----------------
__global__ void xt_kernel(const float* __restrict__ X) {
    __shared__ float t[32][33];
    int b = blockIdx.z;
    int k0 = blockIdx.x * 32, f0 = blockIdx.y * 32;
    int tx = threadIdx.x & 31, ty = threadIdx.x >> 5;   // ty 0..7
    const float* Xb = X + (size_t)b * NN * FF;
#pragma unroll
    for (int i = 0; i < 4; i++)
        t[ty + i * 8][tx] = Xb[(size_t)(k0 + ty + i * 8) * FF + f0 + tx];
    __syncthreads();
    float* Ob = g_Xt + (size_t)b * FF * NN;
#pragma unroll
    for (int i = 0; i < 4; i++)
        Ob[(size_t)(f0 + ty + i * 8) * NN + k0 + tx] = t[tx][ty + i * 8];
}

// ---------------- k1: fused ----------------
__global__ __launch_bounds__(64, 2)
void fused_kernel(const float* __restrict__ A,
                  const float* __restrict__ W,
                  const float* __restrict__ bias, const float* __restrict__ gamma,
                  const float* __restrict__ beta, float* __restrict__ out) {
    extern __shared__ char smem[];
    float* sf = (float*)smem;
    const uint32_t sbu = smem_u32(smem);

    const int tid = threadIdx.x;          // 0..63
    const int lid = tid & 31;
    const int wn  = tid >> 5;             // warp 0/1 -> n-half
    const int gp  = lid >> 2;             // 0..7
    const int tg  = lid & 3;              // 0..3
    const int s   = lid >> 3;             // ldmatrix submatrix id 0..3
    const int rr  = lid & 7;              // row within submatrix
    // A frags: s0=(m+0,k+0) s1=(m+8,k+0) s2=(m+0,k+4) s3=(m+8,k+4)
    const int aR = (s & 1) * 8 + rr;
    const int aC = (s >> 1) * 4;
    // B frags: s0=(n+0,k+0) s1=(n+0,k+4) s2=(n+8,k+0) s3=(n+8,k+4)
    const int bR = (s >> 1) * 8 + rr;
    const int bC = (s & 1) * 4;

    const int bt      = blockIdx.x >> 5;
    const int rowTile = blockIdx.x & 31;
    const float* Ab = A    + (size_t)bt * NN * NN + (size_t)rowTile * ROWS * NN;
    const float* Xb = g_Xt + (size_t)bt * FF * NN;

    float acc[4][8][4];                   // 4 m16 x 8 n8 tiles = 64x64
#pragma unroll
    for (int i = 0; i < 4; i++)
#pragma unroll
        for (int j = 0; j < 8; j++)
#pragma unroll
            for (int k = 0; k < 4; k++) acc[i][j][k] = 0.f;

    // ---- loader: chunk c (64 k-values) -> stage c&1 ----
    auto load_chunk = [&](int c) {
        const int st = c & 1;
        const uint32_t ab = sbu + (uint32_t)st * STAGE_B;
        const uint32_t xb = ab + ST_X_OFF;
        const float* ga = Ab + c * CK;                   // 64 rows x 64 k
        const float* gx = Xb + c * CK;                   // 128 f-rows x 64 k
#pragma unroll
        for (int i = 0; i < 16; i++) {                   // A: 1024 cp16
            int id = tid + i * 64;
            int r = id >> 4, q = id & 15;
            cp16(ab + (uint32_t)(r * PADA + q * 4) * 4u, ga + (size_t)r * NN + q * 4);
        }
#pragma unroll
        for (int i = 0; i < 32; i++) {                   // X: 2048 cp16
            int id = tid + i * 64;
            int r = id >> 4, q = id & 15;
            cp16(xb + (uint32_t)(r * PADA + q * 4) * 4u, gx + (size_t)r * NN + q * 4);
        }
        CP_COMMIT();
    };

    load_chunk(0);
    load_chunk(1);

    // ---- GEMM1 mainloop: 32 chunks of k=64 ----
    for (int c = 0; c < NCH; c++) {
        const int st = c & 1;
        asm volatile("cp.async.wait_group 1;" ::: "memory");
        __syncthreads();

        const uint32_t aBase = sbu + (uint32_t)st * STAGE_B;
        const uint32_t xBase = aBase + ST_X_OFF;
#pragma unroll
        for (int k8 = 0; k8 < 8; k8++) {
            const int kb = k8 * 8;
            uint32_t af[4][4], bf[8][2];
#pragma unroll
            for (int mt = 0; mt < 4; mt++) {
                uint32_t ad = aBase + (uint32_t)((mt * 16 + aR) * PADA + kb + aC) * 4u;
                LDSM_X4(af[mt][0], af[mt][1], af[mt][2], af[mt][3], ad);
            }
#pragma unroll
            for (int p = 0; p < 4; p++) {
                uint32_t bd = xBase + (uint32_t)((wn * 64 + p * 16 + bR) * PADA + kb + bC) * 4u;
                LDSM_X4(bf[p * 2][0], bf[p * 2][1], bf[p * 2 + 1][0], bf[p * 2 + 1][1], bd);
            }
#pragma unroll
            for (int mt = 0; mt < 4; mt++)
#pragma unroll
                for (int nt = 0; nt < 8; nt++)
                    MMA_TF32(acc[mt][nt], af[mt], bf[nt]);
        }
        __syncthreads();                  // stage fully consumed
        if (c + 2 < NCH) load_chunk(c + 2);
        else CP_COMMIT();                 // keep group counts uniform
    }
    asm volatile("cp.async.wait_group 0;" ::: "memory");
    __syncthreads();

    // ---- H (regs) -> smem [64][132] ----
#pragma unroll
    for (int mt = 0; mt < 4; mt++)
#pragma unroll
        for (int nt = 0; nt < 8; nt++) {
            int r  = mt * 16 + gp;
            int cc = wn * 64 + nt * 8 + 2 * tg;
            *(float2*)(sf + (size_t)r * PADH + cc) =
                make_float2(acc[mt][nt][0], acc[mt][nt][1]);
            *(float2*)(sf + (size_t)(r + 8) * PADH + cc) =
                make_float2(acc[mt][nt][2], acc[mt][nt][3]);
        }

    // ---- W [128][128] -> smem [128][132] ----
#pragma unroll
    for (int i = 0; i < 64; i++) {
        int id = tid + i * 64;                // 0..4095 float4
        int d = id >> 5, q = id & 31;
        float4 v = *(const float4*)(W + (size_t)d * FF + q * 4);
        *(float4*)(sf + SM_W_OFF / 4 + (size_t)d * PADH + q * 4) = v;
    }
    {
        float* par = sf + SM_PAR_OFF / 4;
        par[tid]       = bias[tid];  par[tid + 64]        = bias[tid + 64];
        par[128 + tid] = gamma[tid]; par[128 + tid + 64]  = gamma[tid + 64];
        par[256 + tid] = beta[tid];  par[256 + tid + 64]  = beta[tid + 64];
    }
    __syncthreads();

    // ---- GEMM2: O = H @ W^T  (K = 128) ----
#pragma unroll
    for (int i = 0; i < 4; i++)
#pragma unroll
        for (int j = 0; j < 8; j++)
#pragma unroll
            for (int k = 0; k < 4; k++) acc[i][j][k] = 0.f;

    const uint32_t hBase = sbu;
    const uint32_t wBase = sbu + SM_W_OFF;
#pragma unroll
    for (int k8 = 0; k8 < 16; k8++) {
        const int kb = k8 * 8;
        uint32_t af[4][4], bf[8][2];
#pragma unroll
        for (int mt = 0; mt < 4; mt++) {
            uint32_t ad = hBase + (uint32_t)((mt * 16 + aR) * PADH + kb + aC) * 4u;
            LDSM_X4(af[mt][0], af[mt][1], af[mt][2], af[mt][3], ad);
        }
#pragma unroll
        for (int p = 0; p < 4; p++) {
            uint32_t bd = wBase + (uint32_t)((wn * 64 + p * 16 + bR) * PADH + kb + bC) * 4u;
            LDSM_X4(bf[p * 2][0], bf[p * 2][1], bf[p * 2 + 1][0], bf[p * 2 + 1][1], bd);
        }
#pragma unroll
        for (int mt = 0; mt < 4; mt++)
#pragma unroll
            for (int nt = 0; nt < 8; nt++)
                MMA_TF32(acc[mt][nt], af[mt], bf[nt]);
    }

    // ---- epilogue: bias + LayerNorm + ReLU ----
    const float* sbias = sf + SM_PAR_OFF / 4;
    const float* sgam  = sbias + 128;
    const float* sbet  = sbias + 256;

    float s1[4][2], s2[4][2];
#pragma unroll
    for (int mt = 0; mt < 4; mt++) { s1[mt][0] = s1[mt][1] = s2[mt][0] = s2[mt][1] = 0.f; }
#pragma unroll
    for (int mt = 0; mt < 4; mt++)
#pragma unroll
        for (int nt = 0; nt < 8; nt++) {
            int cc = wn * 64 + nt * 8 + 2 * tg;
            float b0 = sbias[cc], b1 = sbias[cc + 1];
            float v0 = acc[mt][nt][0] + b0, v1 = acc[mt][nt][1] + b1;
            float v2 = acc[mt][nt][2] + b0, v3 = acc[mt][nt][3] + b1;
            acc[mt][nt][0] = v0; acc[mt][nt][1] = v1;
            acc[mt][nt][2] = v2; acc[mt][nt][3] = v3;
            s1[mt][0] += v0 + v1;           s2[mt][0] += v0 * v0 + v1 * v1;
            s1[mt][1] += v2 + v3;           s2[mt][1] += v2 * v2 + v3 * v3;
        }
#pragma unroll
    for (int mt = 0; mt < 4; mt++)
#pragma unroll
        for (int h = 0; h < 2; h++) {
            s1[mt][h] += __shfl_xor_sync(0xffffffffu, s1[mt][h], 1);
            s1[mt][h] += __shfl_xor_sync(0xffffffffu, s1[mt][h], 2);
            s2[mt][h] += __shfl_xor_sync(0xffffffffu, s2[mt][h], 1);
            s2[mt][h] += __shfl_xor_sync(0xffffffffu, s2[mt][h], 2);
        }
    float* sred = sf + SM_RED_OFF / 4;
    if (tg == 0) {
#pragma unroll
        for (int mt = 0; mt < 4; mt++)
#pragma unroll
            for (int h = 0; h < 2; h++) {
                int r = mt * 16 + h * 8 + gp;
                sred[r * 4 + wn * 2 + 0] = s1[mt][h];
                sred[r * 4 + wn * 2 + 1] = s2[mt][h];
            }
    }
    __syncthreads();

    float* outBase = out + ((size_t)bt * NN + (size_t)rowTile * ROWS) * FF;
#pragma unroll
    for (int mt = 0; mt < 4; mt++)
#pragma unroll
        for (int h = 0; h < 2; h++) {
            int r = mt * 16 + h * 8 + gp;
            float S1 = sred[r * 4 + 0] + sred[r * 4 + 2];
            float S2 = sred[r * 4 + 1] + sred[r * 4 + 3];
            float mean = S1 * (1.0f / 128.0f);
            float var  = S2 * (1.0f / 128.0f) - mean * mean;
            float inv  = rsqrtf(var + 1e-5f);
            float* orow = outBase + (size_t)r * FF;
#pragma unroll
            for (int nt = 0; nt < 8; nt++) {
                int cc = wn * 64 + nt * 8 + 2 * tg;
                float v0 = acc[mt][nt][h * 2 + 0];
                float v1 = acc[mt][nt][h * 2 + 1];
                float o0 = fmaxf((v0 - mean) * inv * sgam[cc]     + sbet[cc],     0.f);
                float o1 = fmaxf((v1 - mean) * inv * sgam[cc + 1] + sbet[cc + 1], 0.f);
                *(float2*)(orow + cc) = make_float2(o0, o1);
            }
        }
}

// ---------------- launch ----------------
extern "C" void kernel_launch(void* const* d_in, const int* in_sizes, int n_in,
                              void* d_out, int out_size) {
    const float* A     = (const float*)d_in[0];   // [8,2048,2048]
    const float* X     = (const float*)d_in[1];   // [8,2048,128]
    const float* W     = (const float*)d_in[2];   // [128,128]
    const float* bias  = (const float*)d_in[3];
    const float* gamma = (const float*)d_in[4];
    const float* beta  = (const float*)d_in[5];
    float* out = (float*)d_out;

    cudaFuncSetAttribute(fused_kernel, cudaFuncAttributeMaxDynamicSharedMemorySize, SM_TOTAL);

    xt_kernel<<<dim3(NN / 32, FF / 32, BATCH), 256>>>(X);
    fused_kernel<<<BATCH * (NN / ROWS), 64, SM_TOTAL>>>(A, W, bias, gamma, beta, out);
}

// round 11
// speedup vs baseline: 1.3545x; 1.3545x over previous
#include <cuda_runtime.h>
#include <cstdint>

// B=8, N=2048, F=D=128
//   H = A_hat@X ; O = H@W^T + b ; out = relu(LN(O)*gamma+beta)
// Re-associated:  Y = X@W^T (tiny) ;  O = A_hat@Y  ->  LN+ReLU fused epilogue.
//
// k0 y_kernel : Yt[b][d][n] = sum_f X[b][n][f]*W[d][f]  (both operands native
//               k-major; output stored transposed so k1's B operand is k-major)
// k1 fused    : per CTA 64x128 tile of O; 4 warps (32x64 warp tiles) that each
//               load a slice AND compute; 4-stage cp.async ring paced by
//               mbarriers (full: arrive-on-cp.async-complete x128; empty: 4).

#define BATCH 8
#define NN    2048
#define FF    128
#define ROWS  64
#define CK    32
#define NCH   64
#define PADA  36             // stage pitch (36 % 32 == 4 -> LDSM conflict-free)
#define PADW  132            // y_kernel tile pitch

#define ST_Y_OFF  9216       // A part 64*36*4
#define STAGE_B   27648      // + Y part 128*36*4 = 18432
#define SM_MBAR   110592     // full[4] @ +0, empty[4] @ +32
#define SM_PAR    110656     // bias|gamma|beta 3*512
#define SM_RED    112192     // 64 rows x 2 x {s1,s2} = 1024
#define SM_TOTAL  113216     // x2 CTAs = 226432 <= 227KB

#define SM_Y_TOTAL 135168    // y_kernel: W 128*132*4 + X 128*132*4

__device__ __align__(16) float g_Yt[BATCH * FF * NN];   // 8 MB scratch

__device__ __forceinline__ uint32_t smem_u32(const void* p) {
    uint32_t a;
    asm("{ .reg .u64 t; cvta.to.shared.u64 t, %1; cvt.u32.u64 %0, t; }" : "=r"(a) : "l"(p));
    return a;
}
__device__ __forceinline__ void cp16(uint32_t dst, const void* src) {
    asm volatile("cp.async.cg.shared.global [%0], [%1], 16;" :: "r"(dst), "l"(src) : "memory");
}

#define MBAR_INIT(mb, c)  asm volatile("mbarrier.init.shared.b64 [%0], %1;" :: "r"(mb), "r"(c) : "memory")
#define MBAR_ARRIVE(mb)   asm volatile("mbarrier.arrive.shared.b64 _, [%0];" :: "r"(mb) : "memory")
#define CP_ARRIVE(mb)     asm volatile("cp.async.mbarrier.arrive.noinc.shared::cta.b64 [%0];" :: "r"(mb) : "memory")

#define MBAR_WAIT(mb, ph) do {                                                     \
    uint32_t _m = (mb); uint32_t _p = (ph); uint32_t _d;                           \
    asm volatile("{\n\t.reg .pred p;\n\t"                                          \
        "mbarrier.try_wait.parity.acquire.cta.shared::cta.b64 p, [%1], %2;\n\t"    \
        "selp.b32 %0, 1, 0, p;\n\t}" : "=r"(_d) : "r"(_m), "r"(_p) : "memory");    \
    if (!_d) {                                                                     \
        asm volatile("{\n\t.reg .pred P1;\n\t"                                     \
        "W_%=:\n\t"                                                                \
        "mbarrier.try_wait.parity.acquire.cta.shared::cta.b64 P1, [%0], %1, 0x989680;\n\t" \
        "@P1 bra.uni D_%=;\n\tbra.uni W_%=;\n\tD_%=:\n\t}"                         \
        :: "r"(_m), "r"(_p) : "memory");                                           \
    }                                                                              \
} while (0)

#define LDSM_X4(r0, r1, r2, r3, addr)                                           \
    asm volatile("ldmatrix.sync.aligned.m8n8.x4.shared.b16 {%0,%1,%2,%3}, [%4];"\
        : "=r"(r0), "=r"(r1), "=r"(r2), "=r"(r3) : "r"(addr))

#define MMA_TF32(d, av, bv)                                                     \
    asm volatile("mma.sync.aligned.m16n8k8.row.col.f32.tf32.tf32.f32 "          \
        "{%0,%1,%2,%3}, {%4,%5,%6,%7}, {%8,%9}, {%0,%1,%2,%3};"                 \
        : "+f"((d)[0]), "+f"((d)[1]), "+f"((d)[2]), "+f"((d)[3])                \
        : "r"((av)[0]), "r"((av)[1]), "r"((av)[2]), "r"((av)[3]),               \
          "r"((bv)[0]), "r"((bv)[1]))

// ---------------- k0: Yt[b][d][n] = sum_f X[b][n][f] * W[d][f] ----------------
// grid (16 n-tiles, 8 batches), 256 thr, 8 warps (wm 0..3 over d, wn 0..1 over n)
__global__ __launch_bounds__(256, 1)
void y_kernel(const float* __restrict__ X, const float* __restrict__ W) {
    extern __shared__ char ysm[];
    float* sW = (float*)ysm;                         // [128][132]
    float* sX = (float*)(ysm + 67584);               // [128][132]
    const uint32_t wU = smem_u32(sW);
    const uint32_t xU = smem_u32(sX);

    const int tid = threadIdx.x;
    const int lid = tid & 31;
    const int wid = tid >> 5;
    const int wm  = wid >> 1, wn = wid & 1;
    const int gp  = lid >> 2, tg = lid & 3;
    const int s   = lid >> 3, rr = lid & 7;
    const int aR = (s & 1) * 8 + rr, aC = (s >> 1) * 4;
    const int bR = (s >> 1) * 8 + rr, bC = (s & 1) * 4;

    const int n0 = blockIdx.x * 128;
    const int bt = blockIdx.y;
    const float* Xb = X + (size_t)bt * NN * FF + (size_t)n0 * FF;

#pragma unroll
    for (int i = 0; i < 16; i++) {
        int id = tid + i * 256;                      // 0..4095 float4
        int r = id >> 5, q = id & 31;
        *(float4*)(sW + r * PADW + q * 4) = *(const float4*)(W  + (size_t)r * FF + q * 4);
        *(float4*)(sX + r * PADW + q * 4) = *(const float4*)(Xb + (size_t)r * FF + q * 4);
    }
    __syncthreads();

    float acc[2][8][4];
#pragma unroll
    for (int i = 0; i < 2; i++)
#pragma unroll
        for (int j = 0; j < 8; j++)
#pragma unroll
            for (int k = 0; k < 4; k++) acc[i][j][k] = 0.f;

#pragma unroll
    for (int k8 = 0; k8 < 16; k8++) {
        const int kb = k8 * 8;
        uint32_t af[2][4], bf[8][2];
#pragma unroll
        for (int mt = 0; mt < 2; mt++) {
            uint32_t ad = wU + (uint32_t)((wm * 32 + mt * 16 + aR) * PADW + kb + aC) * 4u;
            LDSM_X4(af[mt][0], af[mt][1], af[mt][2], af[mt][3], ad);
        }
#pragma unroll
        for (int p = 0; p < 4; p++) {
            uint32_t bd = xU + (uint32_t)((wn * 64 + p * 16 + bR) * PADW + kb + bC) * 4u;
            LDSM_X4(bf[p * 2][0], bf[p * 2][1], bf[p * 2 + 1][0], bf[p * 2 + 1][1], bd);
        }
#pragma unroll
        for (int mt = 0; mt < 2; mt++)
#pragma unroll
            for (int nt = 0; nt < 8; nt++)
                MMA_TF32(acc[mt][nt], af[mt], bf[nt]);
    }

    // store: Yt[bt][d][n]
    float* Yb = g_Yt + (size_t)bt * FF * NN;
#pragma unroll
    for (int mt = 0; mt < 2; mt++)
#pragma unroll
        for (int h = 0; h < 2; h++) {
            int d = wm * 32 + mt * 16 + h * 8 + gp;
#pragma unroll
            for (int nt = 0; nt < 8; nt++) {
                int n = n0 + wn * 64 + nt * 8 + 2 * tg;
                *(float2*)(Yb + (size_t)d * NN + n) =
                    make_float2(acc[mt][nt][h * 2 + 0], acc[mt][nt][h * 2 + 1]);
            }
        }
}

// ---------------- k1: fused O = A@Yt -> bias+LN+ReLU ----------------
__global__ __launch_bounds__(128, 2)
void fused_kernel(const float* __restrict__ A,
                  const float* __restrict__ bias, const float* __restrict__ gamma,
                  const float* __restrict__ beta, float* __restrict__ out) {
    extern __shared__ char smem[];
    float* sf = (float*)smem;
    const uint32_t sbu = smem_u32(smem);

    const int tid = threadIdx.x;
    const int lid = tid & 31;
    const int wid = tid >> 5;           // 0..3
    const int wm  = wid >> 1;           // 0..1 rows half
    const int wn  = wid & 1;            // 0..1 cols half
    const int gp  = lid >> 2, tg = lid & 3;
    const int s   = lid >> 3, rr = lid & 7;
    const int aR = (s & 1) * 8 + rr, aC = (s >> 1) * 4;
    const int bR = (s >> 1) * 8 + rr, bC = (s & 1) * 4;

    const int bt      = blockIdx.x >> 5;
    const int rowTile = blockIdx.x & 31;
    const float* Ab = A    + (size_t)bt * NN * NN + (size_t)rowTile * ROWS * NN;
    const float* Yb = g_Yt + (size_t)bt * FF * NN;

    // mbarrier init: full[st] count 128 (cp.async arrive from every thread),
    // empty[st] count 4 (one per warp)
    if (tid == 0) {
#pragma unroll
        for (int st = 0; st < 4; st++) {
            MBAR_INIT(sbu + SM_MBAR + st * 8, 128);
            MBAR_INIT(sbu + SM_MBAR + 32 + st * 8, 4);
        }
    }
    sf[SM_PAR / 4 + tid]       = bias[tid];
    sf[SM_PAR / 4 + 128 + tid] = gamma[tid];
    sf[SM_PAR / 4 + 256 + tid] = beta[tid];
    __syncthreads();

    float acc[2][8][4];
#pragma unroll
    for (int i = 0; i < 2; i++)
#pragma unroll
        for (int j = 0; j < 8; j++)
#pragma unroll
            for (int k = 0; k < 4; k++) acc[i][j][k] = 0.f;

    // each warp loads its slice of the stage, then arms full[st] on completion
    auto load_chunk = [&](int c) {
        const int st = c & 3;
        const uint32_t ab = sbu + (uint32_t)st * STAGE_B;
        const uint32_t yb = ab + ST_Y_OFF;
        const float* ga = Ab + c * CK;
        const float* gy = Yb + c * CK;
#pragma unroll
        for (int i = 0; i < 4; i++) {              // A: rows wid*16..+15
            int id = wid * 128 + lid + i * 32;
            int r = id >> 3, q = id & 7;
            cp16(ab + (uint32_t)(r * PADA + q * 4) * 4u, ga + (size_t)r * NN + q * 4);
        }
#pragma unroll
        for (int i = 0; i < 8; i++) {              // Y: rows wid*32..+31
            int id = wid * 256 + lid + i * 32;
            int r = id >> 3, q = id & 7;
            cp16(yb + (uint32_t)(r * PADA + q * 4) * 4u, gy + (size_t)r * NN + q * 4);
        }
        CP_ARRIVE(sbu + SM_MBAR + st * 8);
    };

    load_chunk(0); load_chunk(1); load_chunk(2);

    uint32_t af[2][2][4], bf[2][8][2];             // double-buffered fragments

    auto ldA = [&](uint32_t base, int kb, int buf) {
#pragma unroll
        for (int mt = 0; mt < 2; mt++) {
            uint32_t ad = base + (uint32_t)((wm * 32 + mt * 16 + aR) * PADA + kb + aC) * 4u;
            LDSM_X4(af[buf][mt][0], af[buf][mt][1], af[buf][mt][2], af[buf][mt][3], ad);
        }
    };
    auto ldB = [&](uint32_t base, int kb, int buf) {
#pragma unroll
        for (int p = 0; p < 4; p++) {
            uint32_t bd = base + (uint32_t)((wn * 64 + p * 16 + bR) * PADA + kb + bC) * 4u;
            LDSM_X4(bf[buf][p * 2][0], bf[buf][p * 2][1],
                    bf[buf][p * 2 + 1][0], bf[buf][p * 2 + 1][1], bd);
        }
    };

    for (int c = 0; c < NCH; c++) {
        const int st = c & 3;
        // prefetch chunk c+3 into its stage (back-pressured by empty barrier)
        if (c + 3 < NCH) {
            const int cc = c + 3, st3 = cc & 3;
            if (cc >= 4) MBAR_WAIT(sbu + SM_MBAR + 32 + st3 * 8, ((cc >> 2) - 1) & 1);
            load_chunk(cc);
        }
        // wait for this chunk's data
        MBAR_WAIT(sbu + SM_MBAR + st * 8, (c >> 2) & 1);

        const uint32_t aBase = sbu + (uint32_t)st * STAGE_B;
        const uint32_t yBase = aBase + ST_Y_OFF;
        ldA(aBase, 0, 0); ldB(yBase, 0, 0);
#pragma unroll
        for (int k8 = 0; k8 < 4; k8++) {
            const int cur = k8 & 1;
            if (k8 < 3) { ldA(aBase, (k8 + 1) * 8, cur ^ 1); ldB(yBase, (k8 + 1) * 8, cur ^ 1); }
#pragma unroll
            for (int mt = 0; mt < 2; mt++)
#pragma unroll
                for (int nt = 0; nt < 8; nt++)
                    MMA_TF32(acc[mt][nt], af[cur][mt], bf[cur][nt]);
        }
        if (lid == 0) MBAR_ARRIVE(sbu + SM_MBAR + 32 + st * 8);
    }

    // ---- epilogue: bias + LayerNorm + ReLU ----
    const float* sbias = sf + SM_PAR / 4;
    const float* sgam  = sbias + 128;
    const float* sbet  = sbias + 256;

    float s1[2][2], s2[2][2];
#pragma unroll
    for (int mt = 0; mt < 2; mt++) { s1[mt][0] = s1[mt][1] = s2[mt][0] = s2[mt][1] = 0.f; }
#pragma unroll
    for (int mt = 0; mt < 2; mt++)
#pragma unroll
        for (int nt = 0; nt < 8; nt++) {
            int cc = wn * 64 + nt * 8 + 2 * tg;
            float b0 = sbias[cc], b1 = sbias[cc + 1];
            float v0 = acc[mt][nt][0] + b0, v1 = acc[mt][nt][1] + b1;
            float v2 = acc[mt][nt][2] + b0, v3 = acc[mt][nt][3] + b1;
            acc[mt][nt][0] = v0; acc[mt][nt][1] = v1;
            acc[mt][nt][2] = v2; acc[mt][nt][3] = v3;
            s1[mt][0] += v0 + v1;           s2[mt][0] += v0 * v0 + v1 * v1;
            s1[mt][1] += v2 + v3;           s2[mt][1] += v2 * v2 + v3 * v3;
        }
#pragma unroll
    for (int mt = 0; mt < 2; mt++)
#pragma unroll
        for (int h = 0; h < 2; h++) {
            s1[mt][h] += __shfl_xor_sync(0xffffffffu, s1[mt][h], 1);
            s1[mt][h] += __shfl_xor_sync(0xffffffffu, s1[mt][h], 2);
            s2[mt][h] += __shfl_xor_sync(0xffffffffu, s2[mt][h], 1);
            s2[mt][h] += __shfl_xor_sync(0xffffffffu, s2[mt][h], 2);
        }
    float* sred = sf + SM_RED / 4;
    if (tg == 0) {
#pragma unroll
        for (int mt = 0; mt < 2; mt++)
#pragma unroll
            for (int h = 0; h < 2; h++) {
                int r = wm * 32 + mt * 16 + h * 8 + gp;
                sred[r * 4 + wn * 2 + 0] = s1[mt][h];
                sred[r * 4 + wn * 2 + 1] = s2[mt][h];
            }
    }
    __syncthreads();

    float* outBase = out + ((size_t)bt * NN + (size_t)rowTile * ROWS) * FF;
#pragma unroll
    for (int mt = 0; mt < 2; mt++)
#pragma unroll
        for (int h = 0; h < 2; h++) {
            int r = wm * 32 + mt * 16 + h * 8 + gp;
            float S1 = sred[r * 4 + 0] + sred[r * 4 + 2];
            float S2 = sred[r * 4 + 1] + sred[r * 4 + 3];
            float mean = S1 * (1.0f / 128.0f);
            float var  = S2 * (1.0f / 128.0f) - mean * mean;
            float inv  = rsqrtf(var + 1e-5f);
            float* orow = outBase + (size_t)r * FF;
#pragma unroll
            for (int nt = 0; nt < 8; nt++) {
                int cc = wn * 64 + nt * 8 + 2 * tg;
                float v0 = acc[mt][nt][h * 2 + 0];
                float v1 = acc[mt][nt][h * 2 + 1];
                float o0 = fmaxf((v0 - mean) * inv * sgam[cc]     + sbet[cc],     0.f);
                float o1 = fmaxf((v1 - mean) * inv * sgam[cc + 1] + sbet[cc + 1], 0.f);
                *(float2*)(orow + cc) = make_float2(o0, o1);
            }
        }
}

// ---------------- launch ----------------
extern "C" void kernel_launch(void* const* d_in, const int* in_sizes, int n_in,
                              void* d_out, int out_size) {
    const float* A     = (const float*)d_in[0];   // [8,2048,2048]
    const float* X     = (const float*)d_in[1];   // [8,2048,128]
    const float* W     = (const float*)d_in[2];   // [128,128]
    const float* bias  = (const float*)d_in[3];
    const float* gamma = (const float*)d_in[4];
    const float* beta  = (const float*)d_in[5];
    float* out = (float*)d_out;

    cudaFuncSetAttribute(y_kernel, cudaFuncAttributeMaxDynamicSharedMemorySize, SM_Y_TOTAL);
    cudaFuncSetAttribute(fused_kernel, cudaFuncAttributeMaxDynamicSharedMemorySize, SM_TOTAL);

    y_kernel<<<dim3(16, 8), 256, SM_Y_TOTAL>>>(X, W);
    fused_kernel<<<BATCH * (NN / ROWS), 128, SM_TOTAL>>>(A, bias, gamma, beta, out);
}